// round 9
// baseline (speedup 1.0000x reference)
#include <cuda_runtime.h>
#include <cuda_fp16.h>
#include <cstdint>

#define B_  2
#define L_  512
#define T_  1024
#define E_  2560
#define H_  128
#define F_  (2*E_)   // 5120
#define TSH 48       // halves per (l,h) in ts: q[20] pad[4] k[20] pad[4]

// Scratch (no cudaMalloc allowed)
__device__ __half g_xh [B_*L_*T_];      // x fp16        2 MB
__device__ __half g_wuh[E_*T_];         // W_up fp16     5 MB
__device__ __half g_wph[F_*E_];         // W_proj fp16   26 MB
__device__ __half g_xeh[B_*L_*E_];      // xe fp16       5 MB
__device__ __half g_ts [B_*L_*H_*TSH]; // split q|k fp16 12.6 MB
__device__ int    g_cnt[2];             // persistent-GEMM work counters

// ---------------------------------------------------------------------------
// helpers
// ---------------------------------------------------------------------------
__device__ __forceinline__ uint32_t smem_u32(const void* p) {
    uint32_t a;
    asm("{ .reg .u64 t; cvta.to.shared.u64 t, %1; cvt.u32.u64 %0, t; }"
        : "=r"(a) : "l"(p));
    return a;
}

__device__ __forceinline__ void cp_async16(uint32_t smem, const void* g) {
    asm volatile("cp.async.cg.shared.global [%0], [%1], 16;" :: "r"(smem), "l"(g));
}

__device__ __forceinline__ void ldsm_x4(uint32_t (&r)[4], uint32_t addr) {
    asm volatile("ldmatrix.sync.aligned.m8n8.x4.shared.b16 {%0,%1,%2,%3}, [%4];"
                 : "=r"(r[0]), "=r"(r[1]), "=r"(r[2]), "=r"(r[3]) : "r"(addr));
}

__device__ __forceinline__ void mma_f16(float (&d)[4], const uint32_t (&a)[4],
                                        const uint32_t b0, const uint32_t b1) {
    asm volatile(
        "mma.sync.aligned.m16n8k16.row.col.f32.f16.f16.f32 "
        "{%0,%1,%2,%3}, {%4,%5,%6,%7}, {%8,%9}, {%0,%1,%2,%3};"
        : "+f"(d[0]), "+f"(d[1]), "+f"(d[2]), "+f"(d[3])
        : "r"(a[0]), "r"(a[1]), "r"(a[2]), "r"(a[3]), "r"(b0), "r"(b1));
}

// ---------------------------------------------------------------------------
// counter reset (runs inside the graph every replay)
// ---------------------------------------------------------------------------
__global__ void reset_cnt_kernel() {
    if (threadIdx.x < 2) g_cnt[threadIdx.x] = 0;
}

// ---------------------------------------------------------------------------
// f32 -> f16 conversion (vectorized, grid-stride)
// ---------------------------------------------------------------------------
__global__ void f2h_kernel(const float4* __restrict__ in, uint2* __restrict__ out,
                           int n4)
{
    for (int i = blockIdx.x * blockDim.x + threadIdx.x; i < n4;
         i += gridDim.x * blockDim.x) {
        float4 v = in[i];
        __half2 lo = __floats2half2_rn(v.x, v.y);
        __half2 hi = __floats2half2_rn(v.z, v.w);
        uint2 o;
        o.x = *(const uint32_t*)&lo;
        o.y = *(const uint32_t*)&hi;
        out[i] = o;
    }
}

// ---------------------------------------------------------------------------
// Persistent fp16 GEMM: C[M,N] = A[M,K] * W[N,K]^T. 64x128x32 tiles,
// 4-stage cp.async, tiles pulled via atomic counter (N-tile-major order
// so 16 consecutive tiles share the W tile in L2).
// MODE 0: plain __half row-major out.  MODE 2: split-ts out.
// ---------------------------------------------------------------------------
#define BMT 64
#define BN 128
#define BK 32
#define STAGES 4
#define ROWB 80                      // 32 data halves + 8 pad = 80 B/row
#define A_BYTES (BMT*ROWB)
#define STGB ((BMT+BN)*ROWB)
#define GSMEM_BYTES (STGB*STAGES)    // 61440
#define NMX 16                       // M/BMT = 1024/64

template <int MODE>
__global__ void __launch_bounds__(256, 3) gemm_f16(
    const __half* __restrict__ A, const __half* __restrict__ W,
    __half* __restrict__ C, int N, int K, int NT, int* __restrict__ counter)
{
    extern __shared__ __align__(16) char gsm[];
    __shared__ int s_idx;
    const uint32_t sBase = smem_u32(gsm);

    const int tid  = threadIdx.x;
    const int warp = tid >> 5;
    const int lane = tid & 31;
    const int wm = (warp >> 2) * (BMT / 2);
    const int wn = (warp & 3) * 32;

    const int KT = K / BK;
    const int lrow = tid >> 2;          // 0..63
    const int lch  = (tid & 3) * 8;     // halves offset (16B chunks)

    const int sel  = lane >> 3;
    const int lr8  = lane & 7;
    const int selR = (sel & 1) * 8;
    const int selK = (sel >> 1) * 16;
    const int er = lane >> 2;
    const int ec = (lane & 3) * 2;

    #define LOAD_STAGE(st, kt)                                                  \
    {                                                                           \
        const int kb = (kt) * BK;                                               \
        const uint32_t as = sBase + (st) * STGB;                                \
        const uint32_t ws = as + A_BYTES;                                       \
        cp_async16(as + lrow * ROWB + lch * 2,                                  \
                   &A[(size_t)(m0 + lrow) * K + kb + lch]);                     \
        _Pragma("unroll")                                                       \
        for (int i = 0; i < 2; ++i) {                                           \
            int row = lrow + i * 64;                                            \
            cp_async16(ws + row * ROWB + lch * 2,                               \
                       &W[(size_t)(n0 + row) * K + kb + lch]);                  \
        }                                                                       \
        asm volatile("cp.async.commit_group;");                                 \
    }

    while (true) {
        __syncthreads();   // previous tile fully done with s_idx & smem
        if (tid == 0) s_idx = atomicAdd(counter, 1);
        __syncthreads();
        const int idx = s_idx;
        if (idx >= NT) break;

        const int m0 = (idx % NMX) * BMT;
        const int n0 = (idx / NMX) * BN;

        float acc[2][4][4];
        #pragma unroll
        for (int i = 0; i < 2; ++i)
            #pragma unroll
            for (int j = 0; j < 4; ++j)
                #pragma unroll
                for (int v = 0; v < 4; ++v) acc[i][j][v] = 0.0f;

        LOAD_STAGE(0, 0);
        LOAD_STAGE(1, 1);
        LOAD_STAGE(2, 2);

        for (int kt = 0; kt < KT; ++kt) {
            asm volatile("cp.async.wait_group 2;");
            __syncthreads();

            const int st = kt & 3;
            const uint32_t as = sBase + st * STGB;
            const uint32_t ws = as + A_BYTES;

            #pragma unroll
            for (int s = 0; s < 2; ++s) {
                const int kbyte = s * 32 + selK;
                uint32_t af[2][4];
                #pragma unroll
                for (int i = 0; i < 2; ++i) {
                    int m = wm + i * 16 + selR + lr8;
                    ldsm_x4(af[i], as + m * ROWB + kbyte);
                }
                uint32_t bf[4][2];
                #pragma unroll
                for (int j2 = 0; j2 < 2; ++j2) {
                    uint32_t r[4];
                    int n = wn + j2 * 16 + selR + lr8;
                    ldsm_x4(r, ws + n * ROWB + kbyte);
                    bf[j2*2][0]   = r[0]; bf[j2*2][1]   = r[2];
                    bf[j2*2+1][0] = r[1]; bf[j2*2+1][1] = r[3];
                }
                #pragma unroll
                for (int i = 0; i < 2; ++i)
                    #pragma unroll
                    for (int j = 0; j < 4; ++j)
                        mma_f16(acc[i][j], af[i], bf[j][0], bf[j][1]);
            }
            __syncthreads();

            if (kt + 3 < KT) {
                LOAD_STAGE((kt + 3) & 3, kt + 3);
            } else {
                asm volatile("cp.async.commit_group;");
            }
        }

        #pragma unroll
        for (int i = 0; i < 2; ++i) {
            #pragma unroll
            for (int j = 0; j < 4; ++j) {
                int m = m0 + wm + i * 16 + er;
                int n = n0 + wn + j * 8 + ec;
                if (MODE == 0) {
                    __half2 h0 = __floats2half2_rn(acc[i][j][0], acc[i][j][1]);
                    __half2 h1 = __floats2half2_rn(acc[i][j][2], acc[i][j][3]);
                    *(__half2*)(C + (size_t)m * N + n)       = h0;
                    *(__half2*)(C + (size_t)(m + 8) * N + n) = h1;
                } else {
                    int h  = n / 40;
                    int cc = n % 40;
                    bool isq = cc < 20;
                    int pos = isq ? cc : cc + 4;
                    float s = isq ? 0.22360679774997896f : 1.0f;
                    __half2 h0 = __floats2half2_rn(acc[i][j][0] * s, acc[i][j][1] * s);
                    __half2 h1 = __floats2half2_rn(acc[i][j][2] * s, acc[i][j][3] * s);
                    *(__half2*)(C + ((size_t)m * H_ + h) * TSH + pos)       = h0;
                    *(__half2*)(C + ((size_t)(m + 8) * H_ + h) * TSH + pos) = h1;
                }
            }
        }
    }
    #undef LOAD_STAGE
}

// ---------------------------------------------------------------------------
// Epilogue v6: block = (head-chunk 8h, q-tile 32, b). q regs loaded once;
// k DOUBLE-BUFFERED in smem (LDG for kt+1 overlaps compute of kt; one
// barrier per iteration). smem: 2 x 8 planes x 772 f32 (49408 B dynamic).
// Thread: h = tid&7, qg = (tid>>3)&7 (4 q rows), kg = tid>>6 (8 k rows).
// mask warp-uniform per kk -> skip k load + FMA + bias read when 0.
// ---------------------------------------------------------------------------
#define PLANE 772
#define EPK_WORDS (8*PLANE)
#define EP_SMEM_BYTES (2*EPK_WORDS*4)   // 49408

__global__ void __launch_bounds__(256, 2) attn_epilogue_kernel(
    const __half* __restrict__ ts, const int* __restrict__ mask,
    const float* __restrict__ bias, float* __restrict__ out)
{
    extern __shared__ __align__(16) float ksd[];

    const int b  = blockIdx.z;
    const int q0 = blockIdx.y * 32;
    const int h0 = blockIdx.x * 8;
    const int tid = threadIdx.x;
    const int h  = tid & 7;
    const int qg = (tid >> 3) & 7;   // 4 q rows each
    const int kg = tid >> 6;         // 8 k rows per iter (warp-uniform)
    const int frow = tid >> 3;       // fill: 0..31
    const int fh   = tid & 7;        // fill: 0..7

    const size_t kfill_stride = (size_t)H_ * TSH;   // per +1 k row
    const __half* kfill0 = ts + ((size_t)(b * L_ + frow) * H_ + h0 + fh) * TSH + 24;
    float* kdst = ksd;   // plane base set per buffer below

    // ---- prologue: fill k(0) into buffer 0 ----
    {
        const __half* ksrc = kfill0;
        float* d = ksd + fh * PLANE + frow * 24;
        #pragma unroll
        for (int u = 0; u < 3; ++u) {
            uint4 vk = *(const uint4*)(ksrc + u * 8);
            const __half2* hk = (const __half2*)&vk;
            float2 f0 = __half22float2(hk[0]), f1 = __half22float2(hk[1]);
            float2 f2 = __half22float2(hk[2]), f3 = __half22float2(hk[3]);
            *(float4*)(d + u * 8)     = make_float4(f0.x, f0.y, f1.x, f1.y);
            *(float4*)(d + u * 8 + 4) = make_float4(f2.x, f2.y, f3.x, f3.y);
        }
    }

    // ---- load this thread's 4 q rows (head h0+h) into registers, once ----
    float qv[4][20];
    {
        const size_t qrow_base = (size_t)(b * L_ + q0 + qg * 4) * H_;
        #pragma unroll
        for (int qq = 0; qq < 4; ++qq) {
            const __half* qsrc = ts + (qrow_base + (size_t)qq * H_ + h0 + h) * TSH;
            uint4 v0 = *(const uint4*)qsrc;
            uint4 v1 = *(const uint4*)(qsrc + 8);
            uint2 v2 = *(const uint2*)(qsrc + 16);
            const __half2* p0 = (const __half2*)&v0;
            const __half2* p1 = (const __half2*)&v1;
            const __half2* p2 = (const __half2*)&v2;
            #pragma unroll
            for (int j = 0; j < 4; ++j) {
                float2 f = __half22float2(p0[j]);
                qv[qq][j*2] = f.x; qv[qq][j*2+1] = f.y;
            }
            #pragma unroll
            for (int j = 0; j < 4; ++j) {
                float2 f = __half22float2(p1[j]);
                qv[qq][8+j*2] = f.x; qv[qq][8+j*2+1] = f.y;
            }
            #pragma unroll
            for (int j = 0; j < 2; ++j) {
                float2 f = __half22float2(p2[j]);
                qv[qq][16+j*2] = f.x; qv[qq][16+j*2+1] = f.y;
            }
        }
    }
    __syncthreads();   // k(0) visible

    for (int kt = 0; kt < 16; ++kt) {
        const int k0 = kt * 32;
        const float* kbuf = ksd + (kt & 1) * EPK_WORDS;

        // prefetch k(kt+1) rows into registers (overlaps with compute)
        uint4 pf0, pf1, pf2;
        if (kt < 15) {
            const __half* ksrc = kfill0 + (size_t)(k0 + 32) * kfill_stride;
            pf0 = *(const uint4*)(ksrc);
            pf1 = *(const uint4*)(ksrc + 8);
            pf2 = *(const uint4*)(ksrc + 16);
        }

        int maskr[8];
        #pragma unroll
        for (int kk = 0; kk < 8; ++kk)
            maskr[kk] = mask[b * L_ + k0 + kg * 8 + kk];

        const float* kplane = kbuf + h * PLANE;
        const size_t obase = ((size_t)(b * L_ + q0 + qg * 4) * L_ + k0 + kg * 8) * H_
                           + h0 + h;

        #pragma unroll
        for (int kk = 0; kk < 8; ++kk) {
            size_t okk = obase + (size_t)kk * H_;
            if (maskr[kk]) {       // warp-uniform branch
                float kv[20];
                const float* kp = kplane + (kg * 8 + kk) * 24;
                #pragma unroll
                for (int u = 0; u < 5; ++u)
                    *(float4*)&kv[u * 4] = *(const float4*)(kp + u * 4);
                #pragma unroll
                for (int qq = 0; qq < 4; ++qq) {
                    float a0 = 0.f, a1 = 0.f;
                    #pragma unroll
                    for (int c = 0; c < 10; ++c) {
                        a0 = fmaf(qv[qq][2*c],   kv[2*c],   a0);
                        a1 = fmaf(qv[qq][2*c+1], kv[2*c+1], a1);
                    }
                    size_t oidx = okk + (size_t)qq * (L_ * H_);
                    out[oidx] = (a0 + a1) + bias[oidx];
                }
            } else {
                #pragma unroll
                for (int qq = 0; qq < 4; ++qq)
                    out[okk + (size_t)qq * (L_ * H_)] = 0.0f;
            }
        }

        // convert + store prefetched k(kt+1) into the other buffer
        if (kt < 15) {
            float* d = ksd + ((kt + 1) & 1) * EPK_WORDS + fh * PLANE + frow * 24;
            const __half2* hk0 = (const __half2*)&pf0;
            const __half2* hk1 = (const __half2*)&pf1;
            const __half2* hk2 = (const __half2*)&pf2;
            float2 f0 = __half22float2(hk0[0]), f1 = __half22float2(hk0[1]);
            float2 f2 = __half22float2(hk0[2]), f3 = __half22float2(hk0[3]);
            *(float4*)(d)     = make_float4(f0.x, f0.y, f1.x, f1.y);
            *(float4*)(d + 4) = make_float4(f2.x, f2.y, f3.x, f3.y);
            f0 = __half22float2(hk1[0]); f1 = __half22float2(hk1[1]);
            f2 = __half22float2(hk1[2]); f3 = __half22float2(hk1[3]);
            *(float4*)(d + 8)  = make_float4(f0.x, f0.y, f1.x, f1.y);
            *(float4*)(d + 12) = make_float4(f2.x, f2.y, f3.x, f3.y);
            f0 = __half22float2(hk2[0]); f1 = __half22float2(hk2[1]);
            f2 = __half22float2(hk2[2]); f3 = __half22float2(hk2[3]);
            *(float4*)(d + 16) = make_float4(f0.x, f0.y, f1.x, f1.y);
            *(float4*)(d + 20) = make_float4(f2.x, f2.y, f3.x, f3.y);
        }
        __syncthreads();
    }
}

// ---------------------------------------------------------------------------
// launch
// ---------------------------------------------------------------------------
#define PGRID 444   // 148 SMs x occ 3

extern "C" void kernel_launch(void* const* d_in, const int* in_sizes, int n_in,
                              void* d_out, int out_size)
{
    const float* x      = (const float*)d_in[0];   // (B,L,T)
    const int*   mask   = (const int*)  d_in[1];   // (B,L) int32
    const float* bias   = (const float*)d_in[2];   // (B,L,L,H)
    const float* W_up   = (const float*)d_in[3];   // (E,T)
    const float* W_proj = (const float*)d_in[4];   // (2E,E)
    float* out = (float*)d_out;

    __half *xh, *wuh, *wph, *xeh, *ts;
    int* cnt;
    cudaGetSymbolAddress((void**)&xh,  g_xh);
    cudaGetSymbolAddress((void**)&wuh, g_wuh);
    cudaGetSymbolAddress((void**)&wph, g_wph);
    cudaGetSymbolAddress((void**)&xeh, g_xeh);
    cudaGetSymbolAddress((void**)&ts,  g_ts);
    cudaGetSymbolAddress((void**)&cnt, g_cnt);

    cudaFuncSetAttribute((const void*)gemm_f16<0>,
                         cudaFuncAttributeMaxDynamicSharedMemorySize, GSMEM_BYTES);
    cudaFuncSetAttribute((const void*)gemm_f16<2>,
                         cudaFuncAttributeMaxDynamicSharedMemorySize, GSMEM_BYTES);
    cudaFuncSetAttribute((const void*)attn_epilogue_kernel,
                         cudaFuncAttributeMaxDynamicSharedMemorySize, EP_SMEM_BYTES);

    reset_cnt_kernel<<<1, 32>>>();

    // f32 -> f16 conversions
    f2h_kernel<<<512,  256>>>((const float4*)x,      (uint2*)xh,  B_*L_*T_/4);
    f2h_kernel<<<1024, 256>>>((const float4*)W_up,   (uint2*)wuh, E_*T_/4);
    f2h_kernel<<<2048, 256>>>((const float4*)W_proj, (uint2*)wph, F_*E_/4);

    // GEMM1: xe_h(1024,2560) = x_h @ W_up_h^T   (320 tiles)
    gemm_f16<0><<<PGRID, 256, GSMEM_BYTES>>>(xh, wuh, xeh, E_, T_,
                                             NMX * (E_ / BN), cnt);
    // GEMM2: ts split layout = xe_h @ W_proj_h^T (640 tiles)
    gemm_f16<2><<<PGRID, 256, GSMEM_BYTES>>>(xeh, wph, ts, F_, E_,
                                             NMX * (F_ / BN), cnt + 1);
    // fused q.k^T + bias + mask epilogue
    {
        dim3 grid(H_ / 8, L_ / 32, B_);
        attn_epilogue_kernel<<<grid, 256, EP_SMEM_BYTES>>>(ts, mask, bias, out);
    }
}